// round 1
// baseline (speedup 1.0000x reference)
#include <cuda_runtime.h>
#include <cuda_bf16.h>
#include <math.h>

#define Bv 8
#define Nv 1024
#define Cv 768
#define Hv 12
#define HDv 64
#define Mv (Bv*Nv)   // 8192

// Scratch (allocation-free rule: __device__ globals)
__device__ __align__(16) float g_Q[Bv*Hv*Nv*HDv];   // [B,H,N,64], pre-scaled by 1/8
__device__ __align__(16) float g_K[Bv*Hv*Nv*HDv];   // [B,H,N,64]
__device__ __align__(16) float g_V[Bv*Hv*Nv*HDv];   // [B,H,N,64]
__device__ __align__(16) float g_AO[Bv*Nv*Cv];      // attention out, [B,N,C] with C = h*64+d

// ---------------------------------------------------------------------------
// Kernel 1: QKV GEMM.  X[8192,768] @ W[768,2304] + b  -> route to g_Q/g_K/g_V
// Tile: BM=BN=64, BK=16, 256 threads, 4x4 per thread.
// A stored k-major (transposed) in smem so compute reads are LDS.128.
// ---------------------------------------------------------------------------
__global__ __launch_bounds__(256) void qkv_gemm(const float* __restrict__ X,
                                                const float* __restrict__ W,
                                                const float* __restrict__ bias) {
    __shared__ __align__(16) float AsT[16 * 68];  // [k][row]
    __shared__ __align__(16) float Bs [16 * 68];  // [k][col]
    const int tid = threadIdx.x;
    const int tx = tid & 15, ty = tid >> 4;
    const int rowBase = blockIdx.y * 64;
    const int colBase = blockIdx.x * 64;

    float acc[4][4] = {};

    for (int kb = 0; kb < 768; kb += 16) {
        // load A tile 64x16 (one float4 per thread), transpose into AsT
        {
            const int r  = tid >> 2;          // 0..63
            const int kq = (tid & 3) * 4;     // 0,4,8,12
            float4 v = *reinterpret_cast<const float4*>(X + (size_t)(rowBase + r) * 768 + kb + kq);
            AsT[(kq + 0) * 68 + r] = v.x;
            AsT[(kq + 1) * 68 + r] = v.y;
            AsT[(kq + 2) * 68 + r] = v.z;
            AsT[(kq + 3) * 68 + r] = v.w;
        }
        // load B tile 16x64 (one float4 per thread)
        {
            const int kr = tid >> 4;          // 0..15
            const int jq = (tid & 15) * 4;
            *reinterpret_cast<float4*>(&Bs[kr * 68 + jq]) =
                *reinterpret_cast<const float4*>(W + (size_t)(kb + kr) * 2304 + colBase + jq);
        }
        __syncthreads();
        #pragma unroll
        for (int k = 0; k < 16; k++) {
            float4 a4 = *reinterpret_cast<float4*>(&AsT[k * 68 + 4 * ty]);
            float4 b4 = *reinterpret_cast<float4*>(&Bs [k * 68 + 4 * tx]);
            float av[4] = {a4.x, a4.y, a4.z, a4.w};
            float bw[4] = {b4.x, b4.y, b4.z, b4.w};
            #pragma unroll
            for (int i = 0; i < 4; i++)
                #pragma unroll
                for (int j = 0; j < 4; j++)
                    acc[i][j] += av[i] * bw[j];
        }
        __syncthreads();
    }

    // Epilogue: each 64-col tile lies entirely inside one (which, head) slot
    const int which = colBase / 768;            // 0=q, 1=k, 2=v
    const int h     = (colBase % 768) / 64;     // head
    float* dst = (which == 0) ? g_Q : ((which == 1) ? g_K : g_V);
    const float scale = (which == 0) ? 0.125f : 1.0f;   // q / sqrt(64)
    const int b = rowBase >> 10;                // whole tile in one batch (64 | 1024)

    #pragma unroll
    for (int i = 0; i < 4; i++) {
        const int row = rowBase + 4 * ty + i;
        const int n = row & 1023;
        float4 o;
        o.x = (acc[i][0] + bias[colBase + 4 * tx + 0]) * scale;
        o.y = (acc[i][1] + bias[colBase + 4 * tx + 1]) * scale;
        o.z = (acc[i][2] + bias[colBase + 4 * tx + 2]) * scale;
        o.w = (acc[i][3] + bias[colBase + 4 * tx + 3]) * scale;
        *reinterpret_cast<float4*>(&dst[(((size_t)b * Hv + h) * Nv + n) * HDv + 4 * tx]) = o;
    }
}

// ---------------------------------------------------------------------------
// Kernel 2: Flash attention, fp32. One block = 64 query rows of one (b,h).
// grid = (16, B*H).  Online softmax; K smem buffer reused for P.
// Dynamic smem: QsT + KsT/Ps + Vs = 3 * 64*68 floats = 52224 B.
// ---------------------------------------------------------------------------
__global__ __launch_bounds__(256) void flash_attn() {
    extern __shared__ __align__(16) float sm[];
    float* QsT = sm;              // [d][row]  64x68
    float* KsT = sm + 64 * 68;    // [d][col]  64x68 ; reused as Ps[row][col]
    float* Vs  = sm + 2 * 64 * 68;// [k][d]    64x68

    const int tid = threadIdx.x;
    const int tx = tid & 15, ty = tid >> 4;
    const int bh = blockIdx.y;            // b*12 + h
    const int qt = blockIdx.x;            // query tile

    const float* Qg = g_Q + ((size_t)bh * Nv + qt * 64) * HDv;

    // load Q (64x64) transposed into QsT
    #pragma unroll
    for (int it = 0; it < 4; it++) {
        const int fl = tid + it * 256;
        const int r  = fl >> 4;
        const int dq = (fl & 15) * 4;
        float4 v = *reinterpret_cast<const float4*>(Qg + r * 64 + dq);
        QsT[(dq + 0) * 68 + r] = v.x;
        QsT[(dq + 1) * 68 + r] = v.y;
        QsT[(dq + 2) * 68 + r] = v.z;
        QsT[(dq + 3) * 68 + r] = v.w;
    }

    float Ov[4][4] = {};
    float m_i[4] = {-1e30f, -1e30f, -1e30f, -1e30f};
    float l_i[4] = {};

    for (int kt = 0; kt < 16; kt++) {
        __syncthreads();   // previous PV reads of KsT done; Q load visible (first iter)
        const float* Kg = g_K + ((size_t)bh * Nv + kt * 64) * HDv;
        const float* Vg = g_V + ((size_t)bh * Nv + kt * 64) * HDv;
        #pragma unroll
        for (int it = 0; it < 4; it++) {
            const int fl = tid + it * 256;
            const int r  = fl >> 4;
            const int dq = (fl & 15) * 4;
            float4 v = *reinterpret_cast<const float4*>(Kg + r * 64 + dq);
            KsT[(dq + 0) * 68 + r] = v.x;
            KsT[(dq + 1) * 68 + r] = v.y;
            KsT[(dq + 2) * 68 + r] = v.z;
            KsT[(dq + 3) * 68 + r] = v.w;
            *reinterpret_cast<float4*>(&Vs[r * 68 + dq]) =
                *reinterpret_cast<const float4*>(Vg + r * 64 + dq);
        }
        __syncthreads();

        // S = Q @ K^T  (4x4 per thread)
        float Sv[4][4] = {};
        #pragma unroll
        for (int d = 0; d < 64; d++) {
            float4 a4 = *reinterpret_cast<float4*>(&QsT[d * 68 + 4 * ty]);
            float4 b4 = *reinterpret_cast<float4*>(&KsT[d * 68 + 4 * tx]);
            float av[4] = {a4.x, a4.y, a4.z, a4.w};
            float bw[4] = {b4.x, b4.y, b4.z, b4.w};
            #pragma unroll
            for (int i = 0; i < 4; i++)
                #pragma unroll
                for (int j = 0; j < 4; j++)
                    Sv[i][j] += av[i] * bw[j];
        }

        // row max across 16-lane tx group
        float mt[4];
        #pragma unroll
        for (int i = 0; i < 4; i++) {
            mt[i] = fmaxf(fmaxf(Sv[i][0], Sv[i][1]), fmaxf(Sv[i][2], Sv[i][3]));
        }
        #pragma unroll
        for (int off = 1; off < 16; off <<= 1)
            #pragma unroll
            for (int i = 0; i < 4; i++)
                mt[i] = fmaxf(mt[i], __shfl_xor_sync(0xffffffffu, mt[i], off));

        float scl[4], rs[4];
        #pragma unroll
        for (int i = 0; i < 4; i++) {
            const float mnew = fmaxf(m_i[i], mt[i]);
            scl[i] = __expf(m_i[i] - mnew);
            m_i[i] = mnew;
            float s = 0.f;
            #pragma unroll
            for (int j = 0; j < 4; j++) {
                Sv[i][j] = __expf(Sv[i][j] - mnew);   // reuse Sv as P
                s += Sv[i][j];
            }
            rs[i] = s;
        }
        #pragma unroll
        for (int off = 1; off < 16; off <<= 1)
            #pragma unroll
            for (int i = 0; i < 4; i++)
                rs[i] += __shfl_xor_sync(0xffffffffu, rs[i], off);
        #pragma unroll
        for (int i = 0; i < 4; i++) {
            l_i[i] = l_i[i] * scl[i] + rs[i];
            #pragma unroll
            for (int j = 0; j < 4; j++)
                Ov[i][j] *= scl[i];
        }

        __syncthreads();   // everyone done reading KsT -> reuse as Ps
        #pragma unroll
        for (int i = 0; i < 4; i++) {
            float4 p = make_float4(Sv[i][0], Sv[i][1], Sv[i][2], Sv[i][3]);
            *reinterpret_cast<float4*>(&KsT[(4 * ty + i) * 68 + 4 * tx]) = p;
        }
        __syncthreads();

        // O += P @ V
        #pragma unroll
        for (int k = 0; k < 64; k++) {
            float4 v4 = *reinterpret_cast<float4*>(&Vs[k * 68 + 4 * tx]);
            float vw[4] = {v4.x, v4.y, v4.z, v4.w};
            #pragma unroll
            for (int i = 0; i < 4; i++) {
                const float p = KsT[(4 * ty + i) * 68 + k];   // broadcast
                #pragma unroll
                for (int j = 0; j < 4; j++)
                    Ov[i][j] += p * vw[j];
            }
        }
    }

    // epilogue -> g_AO [B,N,C] with channel = h*64 + d
    const int b = bh / Hv;
    const int h = bh % Hv;
    #pragma unroll
    for (int i = 0; i < 4; i++) {
        const int n = qt * 64 + 4 * ty + i;
        const float inv = 1.0f / l_i[i];
        float4 o = make_float4(Ov[i][0] * inv, Ov[i][1] * inv, Ov[i][2] * inv, Ov[i][3] * inv);
        *reinterpret_cast<float4*>(&g_AO[((size_t)b * Nv + n) * Cv + h * 64 + 4 * tx]) = o;
    }
}

// ---------------------------------------------------------------------------
// Kernel 3: output projection.  g_AO[8192,768] @ proj_w[768,768] + b -> out
// ---------------------------------------------------------------------------
__global__ __launch_bounds__(256) void proj_gemm(const float* __restrict__ W,
                                                 const float* __restrict__ bias,
                                                 float* __restrict__ out) {
    __shared__ __align__(16) float AsT[16 * 68];
    __shared__ __align__(16) float Bs [16 * 68];
    const int tid = threadIdx.x;
    const int tx = tid & 15, ty = tid >> 4;
    const int rowBase = blockIdx.y * 64;
    const int colBase = blockIdx.x * 64;

    float acc[4][4] = {};

    for (int kb = 0; kb < 768; kb += 16) {
        {
            const int r  = tid >> 2;
            const int kq = (tid & 3) * 4;
            float4 v = *reinterpret_cast<const float4*>(g_AO + (size_t)(rowBase + r) * 768 + kb + kq);
            AsT[(kq + 0) * 68 + r] = v.x;
            AsT[(kq + 1) * 68 + r] = v.y;
            AsT[(kq + 2) * 68 + r] = v.z;
            AsT[(kq + 3) * 68 + r] = v.w;
        }
        {
            const int kr = tid >> 4;
            const int jq = (tid & 15) * 4;
            *reinterpret_cast<float4*>(&Bs[kr * 68 + jq]) =
                *reinterpret_cast<const float4*>(W + (size_t)(kb + kr) * 768 + colBase + jq);
        }
        __syncthreads();
        #pragma unroll
        for (int k = 0; k < 16; k++) {
            float4 a4 = *reinterpret_cast<float4*>(&AsT[k * 68 + 4 * ty]);
            float4 b4 = *reinterpret_cast<float4*>(&Bs [k * 68 + 4 * tx]);
            float av[4] = {a4.x, a4.y, a4.z, a4.w};
            float bw[4] = {b4.x, b4.y, b4.z, b4.w};
            #pragma unroll
            for (int i = 0; i < 4; i++)
                #pragma unroll
                for (int j = 0; j < 4; j++)
                    acc[i][j] += av[i] * bw[j];
        }
        __syncthreads();
    }

    #pragma unroll
    for (int i = 0; i < 4; i++) {
        const int row = rowBase + 4 * ty + i;
        float4 o;
        o.x = acc[i][0] + bias[colBase + 4 * tx + 0];
        o.y = acc[i][1] + bias[colBase + 4 * tx + 1];
        o.z = acc[i][2] + bias[colBase + 4 * tx + 2];
        o.w = acc[i][3] + bias[colBase + 4 * tx + 3];
        *reinterpret_cast<float4*>(&out[(size_t)row * 768 + colBase + 4 * tx]) = o;
    }
}

// ---------------------------------------------------------------------------
extern "C" void kernel_launch(void* const* d_in, const int* in_sizes, int n_in,
                              void* d_out, int out_size) {
    const float* x      = (const float*)d_in[0];
    const float* qkv_w  = (const float*)d_in[1];
    const float* qkv_b  = (const float*)d_in[2];
    const float* proj_w = (const float*)d_in[3];
    const float* proj_b = (const float*)d_in[4];
    float* out = (float*)d_out;

    // 1) QKV projection + scatter to per-head layout (Q pre-scaled)
    qkv_gemm<<<dim3(2304 / 64, Mv / 64), 256>>>(x, qkv_w, qkv_b);

    // 2) Flash attention
    const int smem = 3 * 64 * 68 * (int)sizeof(float);   // 52224 B
    cudaFuncSetAttribute(flash_attn, cudaFuncAttributeMaxDynamicSharedMemorySize, smem);
    flash_attn<<<dim3(Nv / 64, Bv * Hv), 256, smem>>>();

    // 3) Output projection
    proj_gemm<<<dim3(Cv / 64, Mv / 64), 256>>>(proj_w, proj_b, out);
}

// round 6
// speedup vs baseline: 1.5131x; 1.5131x over previous
#include <cuda_runtime.h>
#include <cuda_bf16.h>
#include <cstdint>

#define Bv 8
#define Nv 1024
#define Cv 768
#define Hv 12
#define HDv 64
#define Mv (Bv*Nv)   // 8192

// ---------------------------------------------------------------------------
// Scratch (__device__ globals; allocation-free rule)
// ---------------------------------------------------------------------------
__device__ __align__(16) float g_Q[Bv*Hv*Nv*HDv];   // [B,H,N,64], pre-scaled by 1/8
__device__ __align__(16) float g_K[Bv*Hv*Nv*HDv];
__device__ __align__(16) float g_V[Bv*Hv*Nv*HDv];
__device__ __align__(16) float g_AO[Bv*Nv*Cv];      // attention out fp32 [B,N,C]

// bf16 hi/lo split operands
__device__ __align__(16) __nv_bfloat16 gX_hi[Mv*Cv],  gX_lo[Mv*Cv];       // 8192x768
__device__ __align__(16) __nv_bfloat16 gWq_hi[Cv*3*Cv], gWq_lo[Cv*3*Cv];  // 768x2304
__device__ __align__(16) __nv_bfloat16 gWp_hi[Cv*Cv],   gWp_lo[Cv*Cv];    // 768x768
__device__ __align__(16) __nv_bfloat16 gAO_hi[Mv*Cv],   gAO_lo[Mv*Cv];    // 8192x768

// ---------------------------------------------------------------------------
// helpers
// ---------------------------------------------------------------------------
__device__ __forceinline__ uint32_t smem_to_u32(const void* p) {
    uint32_t a;
    asm("{ .reg .u64 t; cvta.to.shared.u64 t, %1; cvt.u32.u64 %0, t; }" : "=r"(a) : "l"(p));
    return a;
}
__device__ __forceinline__ void ldsm4(uint32_t (&r)[4], uint32_t addr) {
    asm volatile("ldmatrix.sync.aligned.m8n8.x4.shared.b16 {%0,%1,%2,%3}, [%4];"
                 : "=r"(r[0]), "=r"(r[1]), "=r"(r[2]), "=r"(r[3]) : "r"(addr));
}
__device__ __forceinline__ void ldsm4t(uint32_t (&r)[4], uint32_t addr) {
    asm volatile("ldmatrix.sync.aligned.m8n8.x4.trans.shared.b16 {%0,%1,%2,%3}, [%4];"
                 : "=r"(r[0]), "=r"(r[1]), "=r"(r[2]), "=r"(r[3]) : "r"(addr));
}
__device__ __forceinline__ void mma_bf16(float (&d)[4], const uint32_t (&a)[4],
                                         uint32_t b0, uint32_t b1) {
    asm volatile("mma.sync.aligned.m16n8k16.row.col.f32.bf16.bf16.f32 "
                 "{%0,%1,%2,%3}, {%4,%5,%6,%7}, {%8,%9}, {%0,%1,%2,%3};"
                 : "+f"(d[0]), "+f"(d[1]), "+f"(d[2]), "+f"(d[3])
                 : "r"(a[0]), "r"(a[1]), "r"(a[2]), "r"(a[3]), "r"(b0), "r"(b1));
}
__device__ __forceinline__ void cp16(uint32_t dst, const void* src) {
    asm volatile("cp.async.ca.shared.global [%0], [%1], 16;"
                 :: "r"(dst), "l"(__cvta_generic_to_global(src)));
}
#define CP_COMMIT() asm volatile("cp.async.commit_group;" ::: "memory")
#define CP_WAIT0()  asm volatile("cp.async.wait_group 0;" ::: "memory")

__device__ __forceinline__ uint32_t pack_bf2(__nv_bfloat16 a, __nv_bfloat16 b) {
    __nv_bfloat162 t; t.x = a; t.y = b;
    return *reinterpret_cast<uint32_t*>(&t);
}

// ---------------------------------------------------------------------------
// fp32 -> bf16 hi/lo split (memory-bound)
// ---------------------------------------------------------------------------
__global__ __launch_bounds__(256) void conv_split(const float4* __restrict__ src,
                                                  uint2* __restrict__ hi,
                                                  uint2* __restrict__ lo, int n4) {
    const int i = blockIdx.x * 256 + threadIdx.x;
    if (i >= n4) return;
    float4 v = src[i];
    __nv_bfloat16 h0 = __float2bfloat16_rn(v.x);
    __nv_bfloat16 h1 = __float2bfloat16_rn(v.y);
    __nv_bfloat16 h2 = __float2bfloat16_rn(v.z);
    __nv_bfloat16 h3 = __float2bfloat16_rn(v.w);
    uint2 hv = make_uint2(pack_bf2(h0, h1), pack_bf2(h2, h3));
    __nv_bfloat16 l0 = __float2bfloat16_rn(v.x - __bfloat162float(h0));
    __nv_bfloat16 l1 = __float2bfloat16_rn(v.y - __bfloat162float(h1));
    __nv_bfloat16 l2 = __float2bfloat16_rn(v.z - __bfloat162float(h2));
    __nv_bfloat16 l3 = __float2bfloat16_rn(v.w - __bfloat162float(h3));
    uint2 lv = make_uint2(pack_bf2(l0, l1), pack_bf2(l2, l3));
    hi[i] = hv;
    lo[i] = lv;
}

// ---------------------------------------------------------------------------
// bf16-split GEMM: C[M,Ncols] = A[M,768] @ Bm[768,Ncols] + bias
// A,B given as pre-split bf16 hi/lo.  CTA tile 128x64, BK=16, 256 threads,
// 8 warps in 4(M) x 2(N), warp tile 32x32.  cp.async double-buffered.
// mode 0: scatter into g_Q/g_K/g_V (Q pre-scaled).  mode 1: write Cout.
// ---------------------------------------------------------------------------
#define SA 48        // A smem row stride (16 bf16 = 32B + 16 pad)
#define SB 144       // B smem row stride (64 bf16 = 128B + 16 pad)
#define OFF_ALO 6144
#define OFF_BHI 12288
#define OFF_BLO 14592
#define STAGE   16896
#define NITER   48

__global__ __launch_bounds__(256) void gemm_mma(const __nv_bfloat16* __restrict__ Ahi,
                                                const __nv_bfloat16* __restrict__ Alo,
                                                const __nv_bfloat16* __restrict__ Bhi,
                                                const __nv_bfloat16* __restrict__ Blo,
                                                const float* __restrict__ bias,
                                                float* __restrict__ Cout,
                                                int ldb, int mode) {
    extern __shared__ __align__(128) char smem[];
    const uint32_t smem_base = smem_to_u32(smem);
    const int tid  = threadIdx.x;
    const int wid  = tid >> 5;
    const int lane = tid & 31;
    const int warpM0 = (wid >> 1) * 32;   // 0,32,64,96
    const int warpN0 = (wid & 1) * 32;    // 0,32
    const int rowBase = blockIdx.y * 128;
    const int colBase = blockIdx.x * 64;

    // ---- cp.async per-thread source/dest setup ----
    // A: 128 rows x 32B -> 256 chunks; thread t handles chunk t for hi and lo.
    const int arow  = tid >> 1;
    const int ahalf = (tid & 1) * 16;   // byte offset in row
    const char* pAhi = reinterpret_cast<const char*>(Ahi) +
                       ((size_t)(rowBase + arow) * 768) * 2 + ahalf;
    const char* pAlo = reinterpret_cast<const char*>(Alo) +
                       ((size_t)(rowBase + arow) * 768) * 2 + ahalf;
    const uint32_t dAhi = smem_base + arow * SA + ahalf;
    const uint32_t dAlo = dAhi + OFF_ALO;
    // B: 16 rows x 128B -> 128 chunks hi (threads 0-127) + 128 lo (128-255)
    const int brow_  = (tid & 127) >> 3;
    const int bchunk = (tid & 7) * 16;
    const char* pB = reinterpret_cast<const char*>((tid < 128) ? Bhi : Blo) +
                     ((size_t)brow_ * ldb + colBase) * 2 + bchunk;
    const uint32_t dB = smem_base + ((tid < 128) ? OFF_BHI : OFF_BLO) +
                        brow_ * SB + bchunk;
    const size_t bstep = (size_t)16 * ldb * 2;   // bytes per k-tile for B

    float acc[2][4][4] = {};   // [mt][nt][reg]

    // ---- prologue: stage 0 ----
    cp16(dAhi, pAhi);
    cp16(dAlo, pAlo);
    cp16(dB,  pB);
    CP_COMMIT();

    #pragma unroll 1
    for (int kt = 0; kt < NITER; kt++) {
        CP_WAIT0();
        __syncthreads();
        if (kt + 1 < NITER) {
            const uint32_t so = ((kt + 1) & 1) * STAGE;
            cp16(dAhi + so, pAhi + (kt + 1) * 32);
            cp16(dAlo + so, pAlo + (kt + 1) * 32);
            cp16(dB  + so, pB  + (size_t)(kt + 1) * bstep);
            CP_COMMIT();
        }
        // ---- compute on buffer (kt & 1) ----
        const uint32_t sb = smem_base + (kt & 1) * STAGE;
        uint32_t bhi[2][4], blo[2][4];
        const uint32_t brow = sb + OFF_BHI + (lane & 15) * SB +
                              (warpN0 + ((lane >> 4) & 1) * 8) * 2;
        ldsm4t(bhi[0], brow);
        ldsm4t(bhi[1], brow + 32);
        ldsm4t(blo[0], brow + (OFF_BLO - OFF_BHI));
        ldsm4t(blo[1], brow + 32 + (OFF_BLO - OFF_BHI));
        const uint32_t arowb = sb + (warpM0 + (lane & 15)) * SA + (lane >> 4) * 16;
        #pragma unroll
        for (int mt = 0; mt < 2; mt++) {
            uint32_t ahi[4], alo[4];
            ldsm4(ahi, arowb + mt * (16 * SA));
            ldsm4(alo, arowb + mt * (16 * SA) + OFF_ALO);
            #pragma unroll
            for (int nb = 0; nb < 2; nb++)
                #pragma unroll
                for (int h = 0; h < 2; h++) {
                    const int nt = nb * 2 + h;
                    mma_bf16(acc[mt][nt], ahi, bhi[nb][2*h], bhi[nb][2*h+1]);
                    mma_bf16(acc[mt][nt], ahi, blo[nb][2*h], blo[nb][2*h+1]);
                    mma_bf16(acc[mt][nt], alo, bhi[nb][2*h], bhi[nb][2*h+1]);
                }
        }
        __syncthreads();
    }

    // ---- epilogue: direct register writeback ----
    if (mode == 0) {
        const int which = colBase / 768;          // whole 64-col tile in one slot
        const int hh = (colBase % 768) / 64;
        float* dst = (which == 0) ? g_Q : ((which == 1) ? g_K : g_V);
        const float scale = (which == 0) ? 0.125f : 1.0f;
        #pragma unroll
        for (int mt = 0; mt < 2; mt++) {
            const int row0 = rowBase + warpM0 + mt * 16 + (lane >> 2);
            #pragma unroll
            for (int nt = 0; nt < 4; nt++) {
                const int c = colBase + warpN0 + nt * 8 + (lane & 3) * 2;
                const float2 bvv = *reinterpret_cast<const float2*>(&bias[c]);
                const int d = c % 64;
                #pragma unroll
                for (int half = 0; half < 2; half++) {
                    const int row = row0 + half * 8;
                    const int b = row >> 10, n = row & 1023;
                    float2 o;
                    o.x = (acc[mt][nt][2*half + 0] + bvv.x) * scale;
                    o.y = (acc[mt][nt][2*half + 1] + bvv.y) * scale;
                    *reinterpret_cast<float2*>(
                        &dst[(((size_t)b * Hv + hh) * Nv + n) * HDv + d]) = o;
                }
            }
        }
    } else {
        #pragma unroll
        for (int mt = 0; mt < 2; mt++) {
            const int row0 = rowBase + warpM0 + mt * 16 + (lane >> 2);
            #pragma unroll
            for (int nt = 0; nt < 4; nt++) {
                const int c = colBase + warpN0 + nt * 8 + (lane & 3) * 2;
                const float2 bvv = *reinterpret_cast<const float2*>(&bias[c]);
                #pragma unroll
                for (int half = 0; half < 2; half++) {
                    const int row = row0 + half * 8;
                    float2 o;
                    o.x = acc[mt][nt][2*half + 0] + bvv.x;
                    o.y = acc[mt][nt][2*half + 1] + bvv.y;
                    *reinterpret_cast<float2*>(&Cout[(size_t)row * 768 + c]) = o;
                }
            }
        }
    }
}

// ---------------------------------------------------------------------------
// Flash attention, fp32 (round-1 version, known good)
// ---------------------------------------------------------------------------
__global__ __launch_bounds__(256) void flash_attn() {
    extern __shared__ __align__(16) float sm[];
    float* QsT = sm;
    float* KsT = sm + 64 * 68;
    float* Vs  = sm + 2 * 64 * 68;

    const int tid = threadIdx.x;
    const int tx = tid & 15, ty = tid >> 4;
    const int bh = blockIdx.y;
    const int qt = blockIdx.x;

    const float* Qg = g_Q + ((size_t)bh * Nv + qt * 64) * HDv;

    #pragma unroll
    for (int it = 0; it < 4; it++) {
        const int fl = tid + it * 256;
        const int r  = fl >> 4;
        const int dq = (fl & 15) * 4;
        float4 v = *reinterpret_cast<const float4*>(Qg + r * 64 + dq);
        QsT[(dq + 0) * 68 + r] = v.x;
        QsT[(dq + 1) * 68 + r] = v.y;
        QsT[(dq + 2) * 68 + r] = v.z;
        QsT[(dq + 3) * 68 + r] = v.w;
    }

    float Ov[4][4] = {};
    float m_i[4] = {-1e30f, -1e30f, -1e30f, -1e30f};
    float l_i[4] = {};

    for (int kt = 0; kt < 16; kt++) {
        __syncthreads();
        const float* Kg = g_K + ((size_t)bh * Nv + kt * 64) * HDv;
        const float* Vg = g_V + ((size_t)bh * Nv + kt * 64) * HDv;
        #pragma unroll
        for (int it = 0; it < 4; it++) {
            const int fl = tid + it * 256;
            const int r  = fl >> 4;
            const int dq = (fl & 15) * 4;
            float4 v = *reinterpret_cast<const float4*>(Kg + r * 64 + dq);
            KsT[(dq + 0) * 68 + r] = v.x;
            KsT[(dq + 1) * 68 + r] = v.y;
            KsT[(dq + 2) * 68 + r] = v.z;
            KsT[(dq + 3) * 68 + r] = v.w;
            *reinterpret_cast<float4*>(&Vs[r * 68 + dq]) =
                *reinterpret_cast<const float4*>(Vg + r * 64 + dq);
        }
        __syncthreads();

        float Sv[4][4] = {};
        #pragma unroll
        for (int d = 0; d < 64; d++) {
            float4 a4 = *reinterpret_cast<float4*>(&QsT[d * 68 + 4 * ty]);
            float4 b4 = *reinterpret_cast<float4*>(&KsT[d * 68 + 4 * tx]);
            float av[4] = {a4.x, a4.y, a4.z, a4.w};
            float bw[4] = {b4.x, b4.y, b4.z, b4.w};
            #pragma unroll
            for (int i = 0; i < 4; i++)
                #pragma unroll
                for (int j = 0; j < 4; j++)
                    Sv[i][j] += av[i] * bw[j];
        }

        float mt[4];
        #pragma unroll
        for (int i = 0; i < 4; i++)
            mt[i] = fmaxf(fmaxf(Sv[i][0], Sv[i][1]), fmaxf(Sv[i][2], Sv[i][3]));
        #pragma unroll
        for (int off = 1; off < 16; off <<= 1)
            #pragma unroll
            for (int i = 0; i < 4; i++)
                mt[i] = fmaxf(mt[i], __shfl_xor_sync(0xffffffffu, mt[i], off));

        float scl[4], rs[4];
        #pragma unroll
        for (int i = 0; i < 4; i++) {
            const float mnew = fmaxf(m_i[i], mt[i]);
            scl[i] = __expf(m_i[i] - mnew);
            m_i[i] = mnew;
            float s = 0.f;
            #pragma unroll
            for (int j = 0; j < 4; j++) {
                Sv[i][j] = __expf(Sv[i][j] - mnew);
                s += Sv[i][j];
            }
            rs[i] = s;
        }
        #pragma unroll
        for (int off = 1; off < 16; off <<= 1)
            #pragma unroll
            for (int i = 0; i < 4; i++)
                rs[i] += __shfl_xor_sync(0xffffffffu, rs[i], off);
        #pragma unroll
        for (int i = 0; i < 4; i++) {
            l_i[i] = l_i[i] * scl[i] + rs[i];
            #pragma unroll
            for (int j = 0; j < 4; j++)
                Ov[i][j] *= scl[i];
        }

        __syncthreads();
        #pragma unroll
        for (int i = 0; i < 4; i++) {
            float4 p = make_float4(Sv[i][0], Sv[i][1], Sv[i][2], Sv[i][3]);
            *reinterpret_cast<float4*>(&KsT[(4 * ty + i) * 68 + 4 * tx]) = p;
        }
        __syncthreads();

        #pragma unroll
        for (int k = 0; k < 64; k++) {
            float4 v4 = *reinterpret_cast<float4*>(&Vs[k * 68 + 4 * tx]);
            float vw[4] = {v4.x, v4.y, v4.z, v4.w};
            #pragma unroll
            for (int i = 0; i < 4; i++) {
                const float p = KsT[(4 * ty + i) * 68 + k];
                #pragma unroll
                for (int j = 0; j < 4; j++)
                    Ov[i][j] += p * vw[j];
            }
        }
    }

    const int b = bh / Hv;
    const int h = bh % Hv;
    #pragma unroll
    for (int i = 0; i < 4; i++) {
        const int n = qt * 64 + 4 * ty + i;
        const float inv = 1.0f / l_i[i];
        float4 o = make_float4(Ov[i][0] * inv, Ov[i][1] * inv, Ov[i][2] * inv, Ov[i][3] * inv);
        *reinterpret_cast<float4*>(&g_AO[((size_t)b * Nv + n) * Cv + h * 64 + 4 * tx]) = o;
    }
}

// ---------------------------------------------------------------------------
extern "C" void kernel_launch(void* const* d_in, const int* in_sizes, int n_in,
                              void* d_out, int out_size) {
    const float* x      = (const float*)d_in[0];
    const float* qkv_w  = (const float*)d_in[1];
    const float* qkv_b  = (const float*)d_in[2];
    const float* proj_w = (const float*)d_in[3];
    const float* proj_b = (const float*)d_in[4];
    float* out = (float*)d_out;

    // device-global addresses (host side)
    __nv_bfloat16 *xh, *xl, *wqh, *wql, *wph, *wpl, *aoh, *aol;
    float* aof;
    cudaGetSymbolAddress((void**)&xh,  gX_hi);
    cudaGetSymbolAddress((void**)&xl,  gX_lo);
    cudaGetSymbolAddress((void**)&wqh, gWq_hi);
    cudaGetSymbolAddress((void**)&wql, gWq_lo);
    cudaGetSymbolAddress((void**)&wph, gWp_hi);
    cudaGetSymbolAddress((void**)&wpl, gWp_lo);
    cudaGetSymbolAddress((void**)&aoh, gAO_hi);
    cudaGetSymbolAddress((void**)&aol, gAO_lo);
    cudaGetSymbolAddress((void**)&aof, g_AO);

    const int gemm_smem = 2 * STAGE;                         // 33792 B
    const int fa_smem   = 3 * 64 * 68 * (int)sizeof(float);  // 52224 B
    cudaFuncSetAttribute(flash_attn, cudaFuncAttributeMaxDynamicSharedMemorySize, fa_smem);

    // 0) split operands to bf16 hi/lo
    {
        int n4 = Mv * Cv / 4;          // X
        conv_split<<<(n4 + 255) / 256, 256>>>((const float4*)x, (uint2*)xh, (uint2*)xl, n4);
        n4 = Cv * 3 * Cv / 4;          // qkv_w
        conv_split<<<(n4 + 255) / 256, 256>>>((const float4*)qkv_w, (uint2*)wqh, (uint2*)wql, n4);
        n4 = Cv * Cv / 4;              // proj_w
        conv_split<<<(n4 + 255) / 256, 256>>>((const float4*)proj_w, (uint2*)wph, (uint2*)wpl, n4);
    }

    // 1) QKV projection + head-layout scatter (Q pre-scaled)
    gemm_mma<<<dim3(2304 / 64, Mv / 128), 256, gemm_smem>>>(
        xh, xl, wqh, wql, qkv_b, nullptr, 2304, 0);

    // 2) Flash attention (fp32 FFMA)
    flash_attn<<<dim3(Nv / 64, Bv * Hv), 256, fa_smem>>>();

    // 3) split AO, then output projection
    {
        int n4 = Mv * Cv / 4;
        conv_split<<<(n4 + 255) / 256, 256>>>((const float4*)aof, (uint2*)aoh, (uint2*)aol, n4);
    }
    gemm_mma<<<dim3(768 / 64, Mv / 128), 256, gemm_smem>>>(
        aoh, aol, wph, wpl, proj_b, out, 768, 1);
}

// round 7
// speedup vs baseline: 2.6092x; 1.7244x over previous
#include <cuda_runtime.h>
#include <cuda_bf16.h>
#include <cstdint>

#define Bv 8
#define Nv 1024
#define Cv 768
#define Hv 12
#define HDv 64
#define Mv (Bv*Nv)   // 8192

// ---------------------------------------------------------------------------
// Scratch (__device__ globals; allocation-free rule)
// ---------------------------------------------------------------------------
__device__ __align__(16) __nv_bfloat16 gQ_hi[Bv*Hv*Nv*HDv], gQ_lo[Bv*Hv*Nv*HDv];
__device__ __align__(16) __nv_bfloat16 gK_hi[Bv*Hv*Nv*HDv], gK_lo[Bv*Hv*Nv*HDv];
__device__ __align__(16) __nv_bfloat16 gV_hi[Bv*Hv*Nv*HDv], gV_lo[Bv*Hv*Nv*HDv];
__device__ __align__(16) __nv_bfloat16 gX_hi[Mv*Cv],  gX_lo[Mv*Cv];
__device__ __align__(16) __nv_bfloat16 gWq_hi[Cv*3*Cv], gWq_lo[Cv*3*Cv];
__device__ __align__(16) __nv_bfloat16 gWp_hi[Cv*Cv],   gWp_lo[Cv*Cv];
__device__ __align__(16) __nv_bfloat16 gAO_hi[Mv*Cv],   gAO_lo[Mv*Cv];

// ---------------------------------------------------------------------------
// helpers
// ---------------------------------------------------------------------------
__device__ __forceinline__ uint32_t smem_to_u32(const void* p) {
    uint32_t a;
    asm("{ .reg .u64 t; cvta.to.shared.u64 t, %1; cvt.u32.u64 %0, t; }" : "=r"(a) : "l"(p));
    return a;
}
__device__ __forceinline__ void ldsm4(uint32_t (&r)[4], uint32_t addr) {
    asm volatile("ldmatrix.sync.aligned.m8n8.x4.shared.b16 {%0,%1,%2,%3}, [%4];"
                 : "=r"(r[0]), "=r"(r[1]), "=r"(r[2]), "=r"(r[3]) : "r"(addr));
}
__device__ __forceinline__ void ldsm4t(uint32_t (&r)[4], uint32_t addr) {
    asm volatile("ldmatrix.sync.aligned.m8n8.x4.trans.shared.b16 {%0,%1,%2,%3}, [%4];"
                 : "=r"(r[0]), "=r"(r[1]), "=r"(r[2]), "=r"(r[3]) : "r"(addr));
}
__device__ __forceinline__ void mma_bf16(float (&d)[4], const uint32_t (&a)[4],
                                         uint32_t b0, uint32_t b1) {
    asm volatile("mma.sync.aligned.m16n8k16.row.col.f32.bf16.bf16.f32 "
                 "{%0,%1,%2,%3}, {%4,%5,%6,%7}, {%8,%9}, {%0,%1,%2,%3};"
                 : "+f"(d[0]), "+f"(d[1]), "+f"(d[2]), "+f"(d[3])
                 : "r"(a[0]), "r"(a[1]), "r"(a[2]), "r"(a[3]), "r"(b0), "r"(b1));
}
__device__ __forceinline__ void cp16(uint32_t dst, const void* src) {
    asm volatile("cp.async.ca.shared.global [%0], [%1], 16;"
                 :: "r"(dst), "l"(__cvta_generic_to_global(src)));
}
#define CP_COMMIT() asm volatile("cp.async.commit_group;" ::: "memory")
#define CP_WAIT0()  asm volatile("cp.async.wait_group 0;" ::: "memory")
#define CP_WAIT1()  asm volatile("cp.async.wait_group 1;" ::: "memory")

__device__ __forceinline__ uint32_t pack_bf2(__nv_bfloat16 a, __nv_bfloat16 b) {
    __nv_bfloat162 t; t.x = a; t.y = b;
    return *reinterpret_cast<uint32_t*>(&t);
}
// split two fp32 into packed bf16 hi pair + lo pair
__device__ __forceinline__ void split_pack(float x, float y, uint32_t& hi, uint32_t& lo) {
    __nv_bfloat16 hx = __float2bfloat16_rn(x);
    __nv_bfloat16 hy = __float2bfloat16_rn(y);
    hi = pack_bf2(hx, hy);
    lo = pack_bf2(__float2bfloat16_rn(x - __bfloat162float(hx)),
                  __float2bfloat16_rn(y - __bfloat162float(hy)));
}

// ---------------------------------------------------------------------------
// fp32 -> bf16 hi/lo split (memory-bound)
// ---------------------------------------------------------------------------
__global__ __launch_bounds__(256) void conv_split(const float4* __restrict__ src,
                                                  uint2* __restrict__ hi,
                                                  uint2* __restrict__ lo, int n4) {
    const int i = blockIdx.x * 256 + threadIdx.x;
    if (i >= n4) return;
    float4 v = src[i];
    uint2 hv, lv;
    split_pack(v.x, v.y, hv.x, lv.x);
    split_pack(v.z, v.w, hv.y, lv.y);
    hi[i] = hv;
    lo[i] = lv;
}

// ---------------------------------------------------------------------------
// bf16-split GEMM: C[M,Ncols] = A[M,768] @ Bm[768,Ncols] + bias
// CTA tile 128x64, BK=16, 256 threads, warp tile 32x32, cp.async x2-buffered.
// mode 0: scatter bf16 hi/lo into gQ/gK/gV (Q pre-scaled).  mode 1: fp32 Cout.
// ---------------------------------------------------------------------------
#define SA 48
#define SB 144
#define OFF_ALO 6144
#define OFF_BHI 12288
#define OFF_BLO 14592
#define STAGE   16896
#define NITER   48

__global__ __launch_bounds__(256) void gemm_mma(const __nv_bfloat16* __restrict__ Ahi,
                                                const __nv_bfloat16* __restrict__ Alo,
                                                const __nv_bfloat16* __restrict__ Bhi,
                                                const __nv_bfloat16* __restrict__ Blo,
                                                const float* __restrict__ bias,
                                                float* __restrict__ Cout,
                                                int ldb, int mode) {
    extern __shared__ __align__(128) char smem[];
    const uint32_t smem_base = smem_to_u32(smem);
    const int tid  = threadIdx.x;
    const int wid  = tid >> 5;
    const int lane = tid & 31;
    const int warpM0 = (wid >> 1) * 32;
    const int warpN0 = (wid & 1) * 32;
    const int rowBase = blockIdx.y * 128;
    const int colBase = blockIdx.x * 64;

    const int arow  = tid >> 1;
    const int ahalf = (tid & 1) * 16;
    const char* pAhi = reinterpret_cast<const char*>(Ahi) +
                       ((size_t)(rowBase + arow) * 768) * 2 + ahalf;
    const char* pAlo = reinterpret_cast<const char*>(Alo) +
                       ((size_t)(rowBase + arow) * 768) * 2 + ahalf;
    const uint32_t dAhi = smem_base + arow * SA + ahalf;
    const uint32_t dAlo = dAhi + OFF_ALO;
    const int brow_  = (tid & 127) >> 3;
    const int bchunk = (tid & 7) * 16;
    const char* pB = reinterpret_cast<const char*>((tid < 128) ? Bhi : Blo) +
                     ((size_t)brow_ * ldb + colBase) * 2 + bchunk;
    const uint32_t dB = smem_base + ((tid < 128) ? OFF_BHI : OFF_BLO) +
                        brow_ * SB + bchunk;
    const size_t bstep = (size_t)16 * ldb * 2;

    float acc[2][4][4] = {};

    cp16(dAhi, pAhi);
    cp16(dAlo, pAlo);
    cp16(dB,  pB);
    CP_COMMIT();

    #pragma unroll 1
    for (int kt = 0; kt < NITER; kt++) {
        CP_WAIT0();
        __syncthreads();
        if (kt + 1 < NITER) {
            const uint32_t so = ((kt + 1) & 1) * STAGE;
            cp16(dAhi + so, pAhi + (kt + 1) * 32);
            cp16(dAlo + so, pAlo + (kt + 1) * 32);
            cp16(dB  + so, pB  + (size_t)(kt + 1) * bstep);
            CP_COMMIT();
        }
        const uint32_t sb = smem_base + (kt & 1) * STAGE;
        uint32_t bhi[2][4], blo[2][4];
        const uint32_t brow = sb + OFF_BHI + (lane & 15) * SB +
                              (warpN0 + ((lane >> 4) & 1) * 8) * 2;
        ldsm4t(bhi[0], brow);
        ldsm4t(bhi[1], brow + 32);
        ldsm4t(blo[0], brow + (OFF_BLO - OFF_BHI));
        ldsm4t(blo[1], brow + 32 + (OFF_BLO - OFF_BHI));
        const uint32_t arowb = sb + (warpM0 + (lane & 15)) * SA + (lane >> 4) * 16;
        #pragma unroll
        for (int mt = 0; mt < 2; mt++) {
            uint32_t ahi[4], alo[4];
            ldsm4(ahi, arowb + mt * (16 * SA));
            ldsm4(alo, arowb + mt * (16 * SA) + OFF_ALO);
            #pragma unroll
            for (int nb = 0; nb < 2; nb++)
                #pragma unroll
                for (int h = 0; h < 2; h++) {
                    const int nt = nb * 2 + h;
                    mma_bf16(acc[mt][nt], ahi, bhi[nb][2*h], bhi[nb][2*h+1]);
                    mma_bf16(acc[mt][nt], ahi, blo[nb][2*h], blo[nb][2*h+1]);
                    mma_bf16(acc[mt][nt], alo, bhi[nb][2*h], bhi[nb][2*h+1]);
                }
        }
        __syncthreads();
    }

    if (mode == 0) {
        const int which = colBase / 768;
        const int hh = (colBase % 768) / 64;
        __nv_bfloat16* dh = (which == 0) ? gQ_hi : ((which == 1) ? gK_hi : gV_hi);
        __nv_bfloat16* dl = (which == 0) ? gQ_lo : ((which == 1) ? gK_lo : gV_lo);
        const float scale = (which == 0) ? 0.125f : 1.0f;
        #pragma unroll
        for (int mt = 0; mt < 2; mt++) {
            const int row0 = rowBase + warpM0 + mt * 16 + (lane >> 2);
            #pragma unroll
            for (int nt = 0; nt < 4; nt++) {
                const int c = colBase + warpN0 + nt * 8 + (lane & 3) * 2;
                const float2 bvv = *reinterpret_cast<const float2*>(&bias[c]);
                const int d = c % 64;
                #pragma unroll
                for (int half = 0; half < 2; half++) {
                    const int row = row0 + half * 8;
                    const int b = row >> 10, n = row & 1023;
                    const float ox = (acc[mt][nt][2*half + 0] + bvv.x) * scale;
                    const float oy = (acc[mt][nt][2*half + 1] + bvv.y) * scale;
                    uint32_t hv, lv;
                    split_pack(ox, oy, hv, lv);
                    const size_t idx = (((size_t)b * Hv + hh) * Nv + n) * HDv + d;
                    *reinterpret_cast<uint32_t*>(&dh[idx]) = hv;
                    *reinterpret_cast<uint32_t*>(&dl[idx]) = lv;
                }
            }
        }
    } else {
        #pragma unroll
        for (int mt = 0; mt < 2; mt++) {
            const int row0 = rowBase + warpM0 + mt * 16 + (lane >> 2);
            #pragma unroll
            for (int nt = 0; nt < 4; nt++) {
                const int c = colBase + warpN0 + nt * 8 + (lane & 3) * 2;
                const float2 bvv = *reinterpret_cast<const float2*>(&bias[c]);
                #pragma unroll
                for (int half = 0; half < 2; half++) {
                    const int row = row0 + half * 8;
                    float2 o;
                    o.x = acc[mt][nt][2*half + 0] + bvv.x;
                    o.y = acc[mt][nt][2*half + 1] + bvv.y;
                    *reinterpret_cast<float2*>(&Cout[(size_t)row * 768 + c]) = o;
                }
            }
        }
    }
}

// ---------------------------------------------------------------------------
// Flash attention via mma.sync bf16 hi/lo split.
// CTA: 128 q rows of one (b,h); 8 warps, each 16 q x full key tile (64).
// 16 key iterations, K/V cp.async double-buffered.  Writes AO as bf16 hi/lo.
// ---------------------------------------------------------------------------
#define SVR 144          // smem row stride ([*][64] bf16 rows: 128B + 16 pad)
#define MAT 9216         // 64 * SVR
#define FSTAGE 36864     // Khi|Klo|Vhi|Vlo
#define QLO_OFF 18432    // Q staging: Qhi rows 0..127 then Qlo

__global__ __launch_bounds__(256) void flash_mma() {
    extern __shared__ __align__(128) char fsm[];
    const uint32_t sb0 = smem_to_u32(fsm);
    const int tid  = threadIdx.x;
    const int wid  = tid >> 5;
    const int lane = tid & 31;
    const int bh = blockIdx.y;          // b*12 + h
    const int qt = blockIdx.x;          // 128-query tile
    const int warpQ0 = wid * 16;

    const size_t qbase  = ((size_t)bh * Nv + qt * 128) * HDv;   // elements
    const size_t kvbase = (size_t)bh * Nv * HDv;

    // ---- stage Q through smem, pick up fragments ----
    #pragma unroll
    for (int c = 0; c < 4; c++) {
        const int idx = tid + c * 256;
        const int row = idx >> 3;
        const int chunk = (idx & 7) * 16;
        cp16(sb0 + row * SVR + chunk,
             reinterpret_cast<const char*>(gQ_hi + qbase + (size_t)row * HDv) + chunk);
        cp16(sb0 + QLO_OFF + row * SVR + chunk,
             reinterpret_cast<const char*>(gQ_lo + qbase + (size_t)row * HDv) + chunk);
    }
    CP_COMMIT();
    CP_WAIT0();
    __syncthreads();

    uint32_t Qh[4][4], Ql[4][4];
    {
        const uint32_t qrow = sb0 + (warpQ0 + (lane & 15)) * SVR + (lane >> 4) * 16;
        #pragma unroll
        for (int t = 0; t < 4; t++) {
            ldsm4(Qh[t], qrow + t * 32);
            ldsm4(Ql[t], qrow + t * 32 + QLO_OFF);
        }
    }
    __syncthreads();

    // ---- K/V loader for key tile kt into stage s ----
    // 4 mats x 64 rows x 8 chunks = 2048 cp16 / 256 threads = 8 each
    // c>>1 selects mat (const under unroll)
    #define LOAD_KV(sbase, key0) do {                                          \
        _Pragma("unroll")                                                      \
        for (int c = 0; c < 8; c++) {                                          \
            const int rem = tid + (c & 1) * 256;                               \
            const int row = rem >> 3;                                          \
            const int chunk = (rem & 7) * 16;                                  \
            const __nv_bfloat16* srcb =                                        \
                ((c >> 1) == 0) ? gK_hi : ((c >> 1) == 1) ? gK_lo :            \
                ((c >> 1) == 2) ? gV_hi : gV_lo;                               \
            cp16((sbase) + (c >> 1) * MAT + row * SVR + chunk,                 \
                 reinterpret_cast<const char*>(                                \
                     srcb + kvbase + (size_t)((key0) + row) * HDv) + chunk);   \
        }                                                                      \
    } while (0)

    LOAD_KV(sb0, 0);
    CP_COMMIT();

    float O[8][4] = {};
    float m0 = -1e30f, m1 = -1e30f, l0 = 0.f, l1 = 0.f;

    #pragma unroll 1
    for (int kt = 0; kt < 16; kt++) {
        const uint32_t scur = sb0 + (kt & 1) * FSTAGE;
        if (kt + 1 < 16) {
            LOAD_KV(sb0 + ((kt + 1) & 1) * FSTAGE, (kt + 1) * 64);
            CP_COMMIT();
            CP_WAIT1();
        } else {
            CP_WAIT0();
        }
        __syncthreads();

        // ---- S = Q @ K^T (3-MMA split), 16q x 64keys per warp ----
        float S[8][4] = {};
        #pragma unroll
        for (int t = 0; t < 4; t++) {           // d k-tiles
            #pragma unroll
            for (int g = 0; g < 4; g++) {       // 16-key groups
                const uint32_t ka = scur +
                    (g * 16 + (lane & 7) + ((lane >> 4) & 1) * 8) * SVR +
                    t * 32 + ((lane >> 3) & 1) * 16;
                uint32_t Kh[4], Kl[4];
                ldsm4(Kh, ka);
                ldsm4(Kl, ka + MAT);
                mma_bf16(S[2*g],   Qh[t], Kh[0], Kh[1]);
                mma_bf16(S[2*g],   Qh[t], Kl[0], Kl[1]);
                mma_bf16(S[2*g],   Ql[t], Kh[0], Kh[1]);
                mma_bf16(S[2*g+1], Qh[t], Kh[2], Kh[3]);
                mma_bf16(S[2*g+1], Qh[t], Kl[2], Kl[3]);
                mma_bf16(S[2*g+1], Ql[t], Kh[2], Kh[3]);
            }
        }

        // ---- online softmax (rows r0 = lane>>2, r1 = r0+8) ----
        float c0 = -1e30f, c1 = -1e30f;
        #pragma unroll
        for (int nt = 0; nt < 8; nt++) {
            c0 = fmaxf(c0, fmaxf(S[nt][0], S[nt][1]));
            c1 = fmaxf(c1, fmaxf(S[nt][2], S[nt][3]));
        }
        c0 = fmaxf(c0, __shfl_xor_sync(0xffffffffu, c0, 1));
        c0 = fmaxf(c0, __shfl_xor_sync(0xffffffffu, c0, 2));
        c1 = fmaxf(c1, __shfl_xor_sync(0xffffffffu, c1, 1));
        c1 = fmaxf(c1, __shfl_xor_sync(0xffffffffu, c1, 2));
        const float mn0 = fmaxf(m0, c0), mn1 = fmaxf(m1, c1);
        const float sc0 = __expf(m0 - mn0), sc1 = __expf(m1 - mn1);
        m0 = mn0; m1 = mn1;
        float s0 = 0.f, s1 = 0.f;
        #pragma unroll
        for (int nt = 0; nt < 8; nt++) {
            S[nt][0] = __expf(S[nt][0] - mn0);
            S[nt][1] = __expf(S[nt][1] - mn0);
            S[nt][2] = __expf(S[nt][2] - mn1);
            S[nt][3] = __expf(S[nt][3] - mn1);
            s0 += S[nt][0] + S[nt][1];
            s1 += S[nt][2] + S[nt][3];
        }
        s0 += __shfl_xor_sync(0xffffffffu, s0, 1);
        s0 += __shfl_xor_sync(0xffffffffu, s0, 2);
        s1 += __shfl_xor_sync(0xffffffffu, s1, 1);
        s1 += __shfl_xor_sync(0xffffffffu, s1, 2);
        l0 = l0 * sc0 + s0;
        l1 = l1 * sc1 + s1;
        #pragma unroll
        for (int nt = 0; nt < 8; nt++) {
            O[nt][0] *= sc0; O[nt][1] *= sc0;
            O[nt][2] *= sc1; O[nt][3] *= sc1;
        }

        // ---- O += P @ V (P frags from S regs, hi/lo split) ----
        #pragma unroll
        for (int kk = 0; kk < 4; kk++) {        // 16-key k-tiles
            uint32_t Ph[4], Pl[4];
            split_pack(S[2*kk][0],   S[2*kk][1],   Ph[0], Pl[0]);
            split_pack(S[2*kk][2],   S[2*kk][3],   Ph[1], Pl[1]);
            split_pack(S[2*kk+1][0], S[2*kk+1][1], Ph[2], Pl[2]);
            split_pack(S[2*kk+1][2], S[2*kk+1][3], Ph[3], Pl[3]);
            #pragma unroll
            for (int j = 0; j < 4; j++) {       // 16-d col groups
                const uint32_t va = scur + 2 * MAT +
                    (kk * 16 + (lane & 15)) * SVR +
                    (j * 16 + ((lane >> 4) & 1) * 8) * 2;
                uint32_t Vh[4], Vl[4];
                ldsm4t(Vh, va);
                ldsm4t(Vl, va + MAT);
                mma_bf16(O[2*j],   Ph, Vh[0], Vh[1]);
                mma_bf16(O[2*j],   Ph, Vl[0], Vl[1]);
                mma_bf16(O[2*j],   Pl, Vh[0], Vh[1]);
                mma_bf16(O[2*j+1], Ph, Vh[2], Vh[3]);
                mma_bf16(O[2*j+1], Ph, Vl[2], Vl[3]);
                mma_bf16(O[2*j+1], Pl, Vh[2], Vh[3]);
            }
        }
        __syncthreads();
    }

    // ---- epilogue: O / l -> AO bf16 hi/lo, channel = h*64 + d ----
    const float inv0 = 1.0f / l0, inv1 = 1.0f / l1;
    const int b = bh / Hv, h = bh % Hv;
    const int q0 = qt * 128 + warpQ0 + (lane >> 2);
    const size_t base0 = ((size_t)(b * 1024 + q0)) * 768 + h * 64;
    #pragma unroll
    for (int nt = 0; nt < 8; nt++) {
        const int col = nt * 8 + (lane & 3) * 2;
        uint32_t hv, lv;
        split_pack(O[nt][0] * inv0, O[nt][1] * inv0, hv, lv);
        *reinterpret_cast<uint32_t*>(&gAO_hi[base0 + col]) = hv;
        *reinterpret_cast<uint32_t*>(&gAO_lo[base0 + col]) = lv;
        split_pack(O[nt][2] * inv1, O[nt][3] * inv1, hv, lv);
        *reinterpret_cast<uint32_t*>(&gAO_hi[base0 + 8 * 768 + col]) = hv;
        *reinterpret_cast<uint32_t*>(&gAO_lo[base0 + 8 * 768 + col]) = lv;
    }
}

// ---------------------------------------------------------------------------
extern "C" void kernel_launch(void* const* d_in, const int* in_sizes, int n_in,
                              void* d_out, int out_size) {
    const float* x      = (const float*)d_in[0];
    const float* qkv_w  = (const float*)d_in[1];
    const float* qkv_b  = (const float*)d_in[2];
    const float* proj_w = (const float*)d_in[3];
    const float* proj_b = (const float*)d_in[4];
    float* out = (float*)d_out;

    __nv_bfloat16 *xh, *xl, *wqh, *wql, *wph, *wpl, *aoh, *aol;
    cudaGetSymbolAddress((void**)&xh,  gX_hi);
    cudaGetSymbolAddress((void**)&xl,  gX_lo);
    cudaGetSymbolAddress((void**)&wqh, gWq_hi);
    cudaGetSymbolAddress((void**)&wql, gWq_lo);
    cudaGetSymbolAddress((void**)&wph, gWp_hi);
    cudaGetSymbolAddress((void**)&wpl, gWp_lo);
    cudaGetSymbolAddress((void**)&aoh, gAO_hi);
    cudaGetSymbolAddress((void**)&aol, gAO_lo);

    const int gemm_smem = 2 * STAGE;     // 33792 B
    const int fa_smem   = 2 * FSTAGE;    // 73728 B (> 48K -> opt-in)
    cudaFuncSetAttribute(flash_mma, cudaFuncAttributeMaxDynamicSharedMemorySize, fa_smem);

    // 0) split inputs to bf16 hi/lo
    {
        int n4 = Mv * Cv / 4;
        conv_split<<<(n4 + 255) / 256, 256>>>((const float4*)x, (uint2*)xh, (uint2*)xl, n4);
        n4 = Cv * 3 * Cv / 4;
        conv_split<<<(n4 + 255) / 256, 256>>>((const float4*)qkv_w, (uint2*)wqh, (uint2*)wql, n4);
        n4 = Cv * Cv / 4;
        conv_split<<<(n4 + 255) / 256, 256>>>((const float4*)proj_w, (uint2*)wph, (uint2*)wpl, n4);
    }

    // 1) QKV projection -> bf16 hi/lo Q/K/V in head layout (Q pre-scaled)
    gemm_mma<<<dim3(2304 / 64, Mv / 128), 256, gemm_smem>>>(
        xh, xl, wqh, wql, qkv_b, nullptr, 2304, 0);

    // 2) Flash attention (tensor cores) -> AO bf16 hi/lo
    flash_mma<<<dim3(Nv / 128, Bv * Hv), 256, fa_smem>>>();

    // 3) Output projection
    gemm_mma<<<dim3(768 / 64, Mv / 128), 256, gemm_smem>>>(
        aoh, aol, wph, wpl, proj_b, out, 768, 1);
}